// round 12
// baseline (speedup 1.0000x reference)
#include <cuda_runtime.h>
#include <cuda_fp16.h>

typedef unsigned long long u64;

#define NN 50000
#define EE 1600000
#define GG 256
#define OUTC 10
#define PAD 128
#define NCHUNK 1563        // ceil(50000/32)

// ---------------- device scratch ----------------
__device__ int g_cnt[2 * NN];          // [0:NN)=row counts, [NN:2NN)=col counts
__device__ int g_padr[NN * PAD];       // edge ids by source (row)
__device__ int g_padc[NN * PAD];       // source node ids by target (col)
__device__ float g_eagg[NN * 32];      // segment_sum(edge_attr, row) — layer-invariant
__device__ __half g_yrelh[NN * 64];    // xc @ W1r, fp16 row-major (gather payload)
__device__ float g_hroot[NN * 64];     // relu(xc @ W1o + b1o)
__device__ float g_xout[NN * 64];
__device__ float g_pooled[GG * 64];

// ---------------- f32x2 helpers ----------------
__device__ __forceinline__ u64 pack2(float lo, float hi) {
    u64 r; asm("mov.b64 %0, {%1,%2};" : "=l"(r) : "f"(lo), "f"(hi)); return r;
}
__device__ __forceinline__ void unpack2(u64 v, float& lo, float& hi) {
    asm("mov.b64 {%0,%1}, %2;" : "=f"(lo), "=f"(hi) : "l"(v));
}
__device__ __forceinline__ void ffma2(u64& d, u64 a, u64 b) {
    asm("fma.rn.f32x2 %0, %1, %2, %0;" : "+l"(d) : "l"(a), "l"(b));
}

// ---------------- padded-bin CSR fill, 4 edges/thread ----------------
__global__ void fill_k(const int* __restrict__ ei) {
    int e = (blockIdx.x * blockDim.x + threadIdx.x) * 4;
    if (e < EE) {
        int4 r4 = *(const int4*)&ei[e];
        int4 c4 = *(const int4*)&ei[EE + e];
        int p;
        p = atomicAdd(&g_cnt[r4.x], 1); if (p < PAD) g_padr[r4.x * PAD + p] = e;
        p = atomicAdd(&g_cnt[r4.y], 1); if (p < PAD) g_padr[r4.y * PAD + p] = e + 1;
        p = atomicAdd(&g_cnt[r4.z], 1); if (p < PAD) g_padr[r4.z * PAD + p] = e + 2;
        p = atomicAdd(&g_cnt[r4.w], 1); if (p < PAD) g_padr[r4.w * PAD + p] = e + 3;
        p = atomicAdd(&g_cnt[NN + c4.x], 1); if (p < PAD) g_padc[c4.x * PAD + p] = r4.x;
        p = atomicAdd(&g_cnt[NN + c4.y], 1); if (p < PAD) g_padc[c4.y * PAD + p] = r4.y;
        p = atomicAdd(&g_cnt[NN + c4.z], 1); if (p < PAD) g_padc[c4.z * PAD + p] = r4.z;
        p = atomicAdd(&g_cnt[NN + c4.w], 1); if (p < PAD) g_padc[c4.w * PAD + p] = r4.w;
    }
}

// ------- edge-attr aggregation: 4 edges/warp-trip, 8 lanes x float4 per edge -------
__global__ void eagg_k(const float* __restrict__ ea) {
    int w = (blockIdx.x * blockDim.x + threadIdx.x) >> 5;
    int lane = threadIdx.x & 31;
    if (w >= NN) return;
    int c = min(g_cnt[w], PAD);
    const int* lst = &g_padr[w * PAD];
    int quad = lane >> 3;        // edge slot 0..3
    int fq = lane & 7;           // float4 index within 32-float row
    float4 acc = make_float4(0.f, 0.f, 0.f, 0.f);
    int k = 0;
    for (; k + 8 <= c; k += 8) {
        int e0 = lst[k + quad];
        int e1 = lst[k + 4 + quad];
        float4 v0 = *(const float4*)&ea[e0 * 32 + fq * 4];
        float4 v1 = *(const float4*)&ea[e1 * 32 + fq * 4];
        acc.x += v0.x + v1.x; acc.y += v0.y + v1.y;
        acc.z += v0.z + v1.z; acc.w += v0.w + v1.w;
    }
    for (; k + 4 <= c; k += 4) {
        int e0 = lst[k + quad];
        float4 v0 = *(const float4*)&ea[e0 * 32 + fq * 4];
        acc.x += v0.x; acc.y += v0.y; acc.z += v0.z; acc.w += v0.w;
    }
    int rem = c - k;
    if (quad < rem) {
        int e0 = lst[k + quad];
        float4 v0 = *(const float4*)&ea[e0 * 32 + fq * 4];
        acc.x += v0.x; acc.y += v0.y; acc.z += v0.z; acc.w += v0.w;
    }
    #pragma unroll
    for (int d = 8; d <= 16; d <<= 1) {
        acc.x += __shfl_xor_sync(0xffffffffu, acc.x, d);
        acc.y += __shfl_xor_sync(0xffffffffu, acc.y, d);
        acc.z += __shfl_xor_sync(0xffffffffu, acc.z, d);
        acc.w += __shfl_xor_sync(0xffffffffu, acc.w, d);
    }
    if (quad == 0) *(float4*)&g_eagg[w * 32 + fq * 4] = acc;
}

// ---------------- mlp_pre: y_rel(fp16) = xc@W1r ; h_root = relu(xc@W1o + b1o) ----------------
#define PRE_WR 0        // 6144 floats
#define PRE_WO 6144     // 6144
#define PRE_IN 12288    // 3072 : [g][k][s] = g*768 + k*8 + s
#define PRE_SMEM ((12288 + 3072) * 4)

__global__ void mlp_pre_k(const float* __restrict__ xprev, int use_xout,
                          const float* __restrict__ W1r,
                          const float* __restrict__ W1o,
                          const float* __restrict__ b1o) {
    extern __shared__ float sm[];
    const float* xin = use_xout ? g_xout : xprev;
    int tid = threadIdx.x;
    for (int i = tid; i < 6144; i += 256) { sm[PRE_WR + i] = W1r[i]; sm[PRE_WO + i] = W1o[i]; }
    int j = tid & 63, grp = tid >> 6;
    float bo = b1o[j];
    __syncthreads();
    for (int chunk = blockIdx.x; chunk < NCHUNK; chunk += gridDim.x) {
        int base = chunk * 32;
        __syncthreads();
        for (int idx = tid; idx < 3072; idx += 256) {
            int nd = idx / 96, k = idx - nd * 96;
            int node = base + nd;
            float v = 0.f;
            if (node < NN) v = (k < 64) ? xin[node * 64 + k] : g_eagg[node * 32 + (k - 64)];
            sm[PRE_IN + (nd >> 3) * 768 + k * 8 + (nd & 7)] = v;
        }
        __syncthreads();
        u64 r0 = 0, r1 = 0, r2 = 0, r3 = 0;
        u64 bop = pack2(bo, bo);
        u64 o0 = bop, o1 = bop, o2 = bop, o3 = bop;
        const float* pin = &sm[PRE_IN + grp * 768];
        #pragma unroll 12
        for (int k = 0; k < 96; k++) {
            ulonglong2 va = *(const ulonglong2*)(pin + k * 8);
            ulonglong2 vb = *(const ulonglong2*)(pin + k * 8 + 4);
            float wrs = sm[PRE_WR + k * 64 + j];
            float wos = sm[PRE_WO + k * 64 + j];
            u64 wr = pack2(wrs, wrs), wo = pack2(wos, wos);
            ffma2(r0, va.x, wr); ffma2(r1, va.y, wr); ffma2(r2, vb.x, wr); ffma2(r3, vb.y, wr);
            ffma2(o0, va.x, wo); ffma2(o1, va.y, wo); ffma2(o2, vb.x, wo); ffma2(o3, vb.y, wo);
        }
        int nb = base + grp * 8;
        if (nb < NN) {     // 50000 % 8 == 0: group fully in-range or fully out
            float v[8];
            unpack2(r0, v[0], v[1]); unpack2(r1, v[2], v[3]);
            unpack2(r2, v[4], v[5]); unpack2(r3, v[6], v[7]);
            bool even = (j & 1) == 0;
            #pragma unroll
            for (int i = 0; i < 8; i++) {
                float other = __shfl_down_sync(0xffffffffu, v[i], 1);
                if (even)
                    *(__half2*)&g_yrelh[(nb + i) * 64 + j] = __floats2half2_rn(v[i], other);
            }
            float a, b;
            unpack2(o0, a, b); g_hroot[(nb + 0) * 64 + j] = fmaxf(a, 0.f); g_hroot[(nb + 1) * 64 + j] = fmaxf(b, 0.f);
            unpack2(o1, a, b); g_hroot[(nb + 2) * 64 + j] = fmaxf(a, 0.f); g_hroot[(nb + 3) * 64 + j] = fmaxf(b, 0.f);
            unpack2(o2, a, b); g_hroot[(nb + 4) * 64 + j] = fmaxf(a, 0.f); g_hroot[(nb + 5) * 64 + j] = fmaxf(b, 0.f);
            unpack2(o3, a, b); g_hroot[(nb + 6) * 64 + j] = fmaxf(a, 0.f); g_hroot[(nb + 7) * 64 + j] = fmaxf(b, 0.f);
        }
    }
}

// ------ mlp_post (fused gather): each warp gathers 4 nodes' y_rel rows,
//        applies relu(+b1r), then block GEMM:
//        xout = relu( relu(agg+b1r)@W2r + h_root@W2o + b2r+b2o ) ------
#define PO_WR  0       // 4096
#define PO_WO  4096    // 4096
#define PO_A   8192    // 2048 : [g][k][s] = g*512 + k*8 + s
#define PO_H   10240   // 2048
#define PO_B1  12288   // 64
#define PO_SCR 12352   // 2048 : [nd][k] node-major scratch
#define PO_SMEM ((12352 + 2048) * 4)

__global__ void __launch_bounds__(256, 3)
mlp_post_k(const float* __restrict__ W2r, const float* __restrict__ b2r,
           const float* __restrict__ W2o, const float* __restrict__ b2o,
           const float* __restrict__ b1r,
           const int* __restrict__ batch, int last) {
    extern __shared__ float sm[];
    int tid = threadIdx.x;
    int lane = tid & 31, warp = tid >> 5;
    for (int i = tid; i < 4096; i += 256) { sm[PO_WR + i] = W2r[i]; sm[PO_WO + i] = W2o[i]; }
    if (tid < 64) sm[PO_B1 + tid] = b1r[tid];
    int j = tid & 63, grp = tid >> 6;
    float b2 = b2r[j] + b2o[j];
    __syncthreads();
    float2 b1v = *(const float2*)&sm[PO_B1 + lane * 2];
    for (int chunk = blockIdx.x; chunk < NCHUNK; chunk += gridDim.x) {
        int base = chunk * 32;
        __syncthreads();
        // phase 1: per-warp gather of 4 nodes (32 lanes x half2 per edge row)
        #pragma unroll
        for (int i = 0; i < 4; i++) {
            int node = base + warp * 4 + i;
            float ax = 0.f, ay = 0.f;
            if (node < NN) {
                int c = min(g_cnt[NN + node], PAD);
                const int* lst = &g_padc[node * PAD];
                int k = 0;
                for (; k + 4 <= c; k += 4) {
                    int4 s4 = *(const int4*)&lst[k];
                    __half2 v0 = *(const __half2*)&g_yrelh[s4.x * 64 + lane * 2];
                    __half2 v1 = *(const __half2*)&g_yrelh[s4.y * 64 + lane * 2];
                    __half2 v2 = *(const __half2*)&g_yrelh[s4.z * 64 + lane * 2];
                    __half2 v3 = *(const __half2*)&g_yrelh[s4.w * 64 + lane * 2];
                    float2 f0 = __half22float2(v0), f1 = __half22float2(v1);
                    float2 f2 = __half22float2(v2), f3 = __half22float2(v3);
                    ax += (f0.x + f1.x) + (f2.x + f3.x);
                    ay += (f0.y + f1.y) + (f2.y + f3.y);
                }
                for (; k < c; k++) {
                    float2 f = __half22float2(*(const __half2*)&g_yrelh[lst[k] * 64 + lane * 2]);
                    ax += f.x; ay += f.y;
                }
            }
            ax = fmaxf(ax + b1v.x, 0.f);
            ay = fmaxf(ay + b1v.y, 0.f);
            *(float2*)&sm[PO_SCR + (warp * 4 + i) * 64 + lane * 2] = make_float2(ax, ay);
        }
        __syncthreads();
        // phase 2: stage A from scratch (transpose to [g][k][s]) + H from global
        for (int idx = tid; idx < 2048; idx += 256) {
            int nd = idx >> 6, k = idx & 63;
            sm[PO_A + (nd >> 3) * 512 + k * 8 + (nd & 7)] = sm[PO_SCR + idx];
            int node = base + nd;
            float h = (node < NN) ? g_hroot[node * 64 + k] : 0.f;
            sm[PO_H + (nd >> 3) * 512 + k * 8 + (nd & 7)] = h;
        }
        __syncthreads();
        u64 bp = pack2(b2, b2);
        u64 c0 = bp, c1 = bp, c2 = bp, c3 = bp;
        const float* pa = &sm[PO_A + grp * 512];
        const float* ph = &sm[PO_H + grp * 512];
        #pragma unroll 16
        for (int k = 0; k < 64; k++) {
            ulonglong2 va = *(const ulonglong2*)(pa + k * 8);
            ulonglong2 vb = *(const ulonglong2*)(pa + k * 8 + 4);
            ulonglong2 ha = *(const ulonglong2*)(ph + k * 8);
            ulonglong2 hb = *(const ulonglong2*)(ph + k * 8 + 4);
            float wrs = sm[PO_WR + k * 64 + j];
            float wos = sm[PO_WO + k * 64 + j];
            u64 wr = pack2(wrs, wrs), wo = pack2(wos, wos);
            ffma2(c0, va.x, wr); ffma2(c1, va.y, wr); ffma2(c2, vb.x, wr); ffma2(c3, vb.y, wr);
            ffma2(c0, ha.x, wo); ffma2(c1, ha.y, wo); ffma2(c2, hb.x, wo); ffma2(c3, hb.y, wo);
        }
        int nb = base + grp * 8;
        if (nb < NN) {
            float v[8];
            unpack2(c0, v[0], v[1]); unpack2(c1, v[2], v[3]);
            unpack2(c2, v[4], v[5]); unpack2(c3, v[6], v[7]);
            if (!last) {
                #pragma unroll
                for (int s = 0; s < 8; s++)
                    g_xout[(nb + s) * 64 + j] = fmaxf(v[s], 0.f);
            } else {
                #pragma unroll
                for (int s = 0; s < 8; s++)
                    atomicAdd(&g_pooled[batch[nb + s] * 64 + j], fmaxf(v[s], 0.f));
            }
        }
    }
}

// ---------------- final MLP ----------------
__global__ void fin_k(const float* __restrict__ W1, const float* __restrict__ b1,
                      const float* __restrict__ W2, const float* __restrict__ b2,
                      float* __restrict__ out) {
    __shared__ float p[64], h[64];
    int g = blockIdx.x, t = threadIdx.x;
    p[t] = g_pooled[g * 64 + t];
    __syncthreads();
    float a = b1[t];
    #pragma unroll
    for (int k = 0; k < 64; k++) a = fmaf(p[k], W1[k * 64 + t], a);
    h[t] = fmaxf(a, 0.f);
    __syncthreads();
    if (t < OUTC) {
        float o = b2[t];
        #pragma unroll
        for (int k = 0; k < 64; k++) o = fmaf(h[k], W2[k * OUTC + t], o);
        out[g * OUTC + t] = o;
    }
}

// ---------------- launch ----------------
extern "C" void kernel_launch(void* const* d_in, const int* in_sizes, int n_in,
                              void* d_out, int out_size) {
    const float* x  = (const float*)d_in[0];
    const float* ea = (const float*)d_in[1];
    const float* L[2][8];
    for (int l = 0; l < 2; l++)
        for (int i = 0; i < 8; i++)
            L[l][i] = (const float*)d_in[2 + l * 8 + i];
    const float* finW1 = (const float*)d_in[18];
    const float* finb1 = (const float*)d_in[19];
    const float* finW2 = (const float*)d_in[20];
    const float* finb2 = (const float*)d_in[21];
    const int* ei    = (const int*)d_in[22];
    const int* batch = (const int*)d_in[23];
    float* out = (float*)d_out;

    cudaFuncSetAttribute(mlp_pre_k, cudaFuncAttributeMaxDynamicSharedMemorySize, PRE_SMEM);
    cudaFuncSetAttribute(mlp_post_k, cudaFuncAttributeMaxDynamicSharedMemorySize, PO_SMEM);

    void* cntp = 0; void* poolp = 0;
    cudaGetSymbolAddress(&cntp, g_cnt);
    cudaGetSymbolAddress(&poolp, g_pooled);
    cudaMemsetAsync(cntp, 0, 2 * NN * sizeof(int));
    cudaMemsetAsync(poolp, 0, GG * 64 * sizeof(float));

    fill_k<<<(EE / 4 + 255) / 256, 256>>>(ei);
    eagg_k<<<6250, 256>>>(ea);

    for (int l = 0; l < 2; l++) {
        mlp_pre_k<<<444, 256, PRE_SMEM>>>(x, l, L[l][0], L[l][4], L[l][5]);
        mlp_post_k<<<444, 256, PO_SMEM>>>(L[l][2], L[l][3], L[l][6], L[l][7],
                                          L[l][1], batch, l == 1);
    }
    fin_k<<<GG, 64>>>(finW1, finb1, finW2, finb2, out);
}

// round 13
// speedup vs baseline: 1.0076x; 1.0076x over previous
#include <cuda_runtime.h>
#include <cuda_fp16.h>

typedef unsigned long long u64;

#define NN 50000
#define EE 1600000
#define GG 256
#define OUTC 10
#define PAD 128
#define NCHUNK 1563        // ceil(50000/32)

// ---------------- device scratch ----------------
__device__ int g_cnt[2 * NN];          // [0:NN)=row counts, [NN:2NN)=col counts
__device__ int g_padr[NN * PAD];       // edge ids by source (row)
__device__ int g_padc[NN * PAD];       // source node ids by target (col)
__device__ float g_eagg[NN * 32];      // segment_sum(edge_attr, row) — layer-invariant
__device__ __half g_yrelh[NN * 64];    // xc @ W1r, fp16 row-major (gather payload)
__device__ float g_hroot[NN * 64];     // relu(xc @ W1o + b1o)
__device__ float g_agg[NN * 64];       // aggregated y_rel (f32)
__device__ float g_xout[NN * 64];
__device__ float g_pooled[GG * 64];

struct alignas(8) h2x2 { __half2 a, b; };

// ---------------- f32x2 helpers ----------------
__device__ __forceinline__ u64 pack2(float lo, float hi) {
    u64 r; asm("mov.b64 %0, {%1,%2};" : "=l"(r) : "f"(lo), "f"(hi)); return r;
}
__device__ __forceinline__ void unpack2(u64 v, float& lo, float& hi) {
    asm("mov.b64 {%0,%1}, %2;" : "=f"(lo), "=f"(hi) : "l"(v));
}
__device__ __forceinline__ void ffma2(u64& d, u64 a, u64 b) {
    asm("fma.rn.f32x2 %0, %1, %2, %0;" : "+l"(d) : "l"(a), "l"(b));
}

// ---------------- padded-bin CSR fill, 4 edges/thread ----------------
__global__ void fill_k(const int* __restrict__ ei) {
    int e = (blockIdx.x * blockDim.x + threadIdx.x) * 4;
    if (e < EE) {
        int4 r4 = *(const int4*)&ei[e];
        int4 c4 = *(const int4*)&ei[EE + e];
        int p;
        p = atomicAdd(&g_cnt[r4.x], 1); if (p < PAD) g_padr[r4.x * PAD + p] = e;
        p = atomicAdd(&g_cnt[r4.y], 1); if (p < PAD) g_padr[r4.y * PAD + p] = e + 1;
        p = atomicAdd(&g_cnt[r4.z], 1); if (p < PAD) g_padr[r4.z * PAD + p] = e + 2;
        p = atomicAdd(&g_cnt[r4.w], 1); if (p < PAD) g_padr[r4.w * PAD + p] = e + 3;
        p = atomicAdd(&g_cnt[NN + c4.x], 1); if (p < PAD) g_padc[c4.x * PAD + p] = r4.x;
        p = atomicAdd(&g_cnt[NN + c4.y], 1); if (p < PAD) g_padc[c4.y * PAD + p] = r4.y;
        p = atomicAdd(&g_cnt[NN + c4.z], 1); if (p < PAD) g_padc[c4.z * PAD + p] = r4.z;
        p = atomicAdd(&g_cnt[NN + c4.w], 1); if (p < PAD) g_padc[c4.w * PAD + p] = r4.w;
    }
}

// ------- edge-attr aggregation: 4 edges/warp-trip, 8 lanes x float4 per edge -------
__global__ void eagg_k(const float* __restrict__ ea) {
    int w = (blockIdx.x * blockDim.x + threadIdx.x) >> 5;
    int lane = threadIdx.x & 31;
    if (w >= NN) return;
    int c = min(g_cnt[w], PAD);
    const int* lst = &g_padr[w * PAD];
    int quad = lane >> 3;        // edge slot 0..3
    int fq = lane & 7;           // float4 index within 32-float row
    float4 acc = make_float4(0.f, 0.f, 0.f, 0.f);
    int k = 0;
    for (; k + 8 <= c; k += 8) {
        int e0 = lst[k + quad];
        int e1 = lst[k + 4 + quad];
        float4 v0 = *(const float4*)&ea[e0 * 32 + fq * 4];
        float4 v1 = *(const float4*)&ea[e1 * 32 + fq * 4];
        acc.x += v0.x + v1.x; acc.y += v0.y + v1.y;
        acc.z += v0.z + v1.z; acc.w += v0.w + v1.w;
    }
    for (; k + 4 <= c; k += 4) {
        int e0 = lst[k + quad];
        float4 v0 = *(const float4*)&ea[e0 * 32 + fq * 4];
        acc.x += v0.x; acc.y += v0.y; acc.z += v0.z; acc.w += v0.w;
    }
    int rem = c - k;
    if (quad < rem) {
        int e0 = lst[k + quad];
        float4 v0 = *(const float4*)&ea[e0 * 32 + fq * 4];
        acc.x += v0.x; acc.y += v0.y; acc.z += v0.z; acc.w += v0.w;
    }
    #pragma unroll
    for (int d = 8; d <= 16; d <<= 1) {
        acc.x += __shfl_xor_sync(0xffffffffu, acc.x, d);
        acc.y += __shfl_xor_sync(0xffffffffu, acc.y, d);
        acc.z += __shfl_xor_sync(0xffffffffu, acc.z, d);
        acc.w += __shfl_xor_sync(0xffffffffu, acc.w, d);
    }
    if (quad == 0) *(float4*)&g_eagg[w * 32 + fq * 4] = acc;
}

// ---------------- mlp_pre: y_rel(fp16) = xc@W1r ; h_root = relu(xc@W1o + b1o) ----------------
#define PRE_WR 0        // 6144 floats
#define PRE_WO 6144     // 6144
#define PRE_IN 12288    // 3072 : [g][k][s] = g*768 + k*8 + s
#define PRE_SMEM ((12288 + 3072) * 4)

__global__ void mlp_pre_k(const float* __restrict__ xprev, int use_xout,
                          const float* __restrict__ W1r,
                          const float* __restrict__ W1o,
                          const float* __restrict__ b1o) {
    extern __shared__ float sm[];
    const float* xin = use_xout ? g_xout : xprev;
    int tid = threadIdx.x;
    for (int i = tid; i < 6144; i += 256) { sm[PRE_WR + i] = W1r[i]; sm[PRE_WO + i] = W1o[i]; }
    int j = tid & 63, grp = tid >> 6;
    float bo = b1o[j];
    __syncthreads();
    for (int chunk = blockIdx.x; chunk < NCHUNK; chunk += gridDim.x) {
        int base = chunk * 32;
        __syncthreads();
        for (int idx = tid; idx < 3072; idx += 256) {
            int nd = idx / 96, k = idx - nd * 96;
            int node = base + nd;
            float v = 0.f;
            if (node < NN) v = (k < 64) ? xin[node * 64 + k] : g_eagg[node * 32 + (k - 64)];
            sm[PRE_IN + (nd >> 3) * 768 + k * 8 + (nd & 7)] = v;
        }
        __syncthreads();
        u64 r0 = 0, r1 = 0, r2 = 0, r3 = 0;
        u64 bop = pack2(bo, bo);
        u64 o0 = bop, o1 = bop, o2 = bop, o3 = bop;
        const float* pin = &sm[PRE_IN + grp * 768];
        #pragma unroll 12
        for (int k = 0; k < 96; k++) {
            ulonglong2 va = *(const ulonglong2*)(pin + k * 8);
            ulonglong2 vb = *(const ulonglong2*)(pin + k * 8 + 4);
            float wrs = sm[PRE_WR + k * 64 + j];
            float wos = sm[PRE_WO + k * 64 + j];
            u64 wr = pack2(wrs, wrs), wo = pack2(wos, wos);
            ffma2(r0, va.x, wr); ffma2(r1, va.y, wr); ffma2(r2, vb.x, wr); ffma2(r3, vb.y, wr);
            ffma2(o0, va.x, wo); ffma2(o1, va.y, wo); ffma2(o2, vb.x, wo); ffma2(o3, vb.y, wo);
        }
        int nb = base + grp * 8;
        if (nb < NN) {     // 50000 % 8 == 0: group fully in-range or fully out
            float v[8];
            unpack2(r0, v[0], v[1]); unpack2(r1, v[2], v[3]);
            unpack2(r2, v[4], v[5]); unpack2(r3, v[6], v[7]);
            bool even = (j & 1) == 0;
            #pragma unroll
            for (int i = 0; i < 8; i++) {
                float other = __shfl_down_sync(0xffffffffu, v[i], 1);
                if (even)
                    *(__half2*)&g_yrelh[(nb + i) * 64 + j] = __floats2half2_rn(v[i], other);
            }
            float a, b;
            unpack2(o0, a, b); g_hroot[(nb + 0) * 64 + j] = fmaxf(a, 0.f); g_hroot[(nb + 1) * 64 + j] = fmaxf(b, 0.f);
            unpack2(o1, a, b); g_hroot[(nb + 2) * 64 + j] = fmaxf(a, 0.f); g_hroot[(nb + 3) * 64 + j] = fmaxf(b, 0.f);
            unpack2(o2, a, b); g_hroot[(nb + 4) * 64 + j] = fmaxf(a, 0.f); g_hroot[(nb + 5) * 64 + j] = fmaxf(b, 0.f);
            unpack2(o3, a, b); g_hroot[(nb + 6) * 64 + j] = fmaxf(a, 0.f); g_hroot[(nb + 7) * 64 + j] = fmaxf(b, 0.f);
        }
    }
}

// ------- gather: 2 edges/half-warp slot per step, fp16 depth-2 add tree,
//         f32 accumulation of 4-edge partial sums -------
__global__ void gather_k() {
    int w = (blockIdx.x * blockDim.x + threadIdx.x) >> 5;
    int lane = threadIdx.x & 31;
    if (w >= NN) return;
    int c = min(g_cnt[NN + w], PAD);
    const int* lst = &g_padc[w * PAD];
    int half = lane >> 4;        // edge slot 0..1
    int fq = lane & 15;          // 4-half group index within 64-half row
    float4 acc = make_float4(0.f, 0.f, 0.f, 0.f);
    int k = 0;
    for (; k + 8 <= c; k += 8) {
        int s0 = lst[k + half];
        int s1 = lst[k + 2 + half];
        int s2 = lst[k + 4 + half];
        int s3 = lst[k + 6 + half];
        h2x2 v0 = *(const h2x2*)&g_yrelh[s0 * 64 + fq * 4];
        h2x2 v1 = *(const h2x2*)&g_yrelh[s1 * 64 + fq * 4];
        h2x2 v2 = *(const h2x2*)&g_yrelh[s2 * 64 + fq * 4];
        h2x2 v3 = *(const h2x2*)&g_yrelh[s3 * 64 + fq * 4];
        // depth-2 fp16 tree over the 4 edges, then one f32 accumulate
        __half2 sa = __hadd2(__hadd2(v0.a, v1.a), __hadd2(v2.a, v3.a));
        __half2 sb = __hadd2(__hadd2(v0.b, v1.b), __hadd2(v2.b, v3.b));
        float2 fa = __half22float2(sa);
        float2 fb = __half22float2(sb);
        acc.x += fa.x; acc.y += fa.y; acc.z += fb.x; acc.w += fb.y;
    }
    for (; k + 2 <= c; k += 2) {
        int s0 = lst[k + half];
        h2x2 v0 = *(const h2x2*)&g_yrelh[s0 * 64 + fq * 4];
        float2 fa = __half22float2(v0.a), fb = __half22float2(v0.b);
        acc.x += fa.x; acc.y += fa.y; acc.z += fb.x; acc.w += fb.y;
    }
    if (k < c && half == 0) {
        int s0 = lst[k];
        h2x2 v0 = *(const h2x2*)&g_yrelh[s0 * 64 + fq * 4];
        float2 fa = __half22float2(v0.a), fb = __half22float2(v0.b);
        acc.x += fa.x; acc.y += fa.y; acc.z += fb.x; acc.w += fb.y;
    }
    acc.x += __shfl_xor_sync(0xffffffffu, acc.x, 16);
    acc.y += __shfl_xor_sync(0xffffffffu, acc.y, 16);
    acc.z += __shfl_xor_sync(0xffffffffu, acc.z, 16);
    acc.w += __shfl_xor_sync(0xffffffffu, acc.w, 16);
    if (half == 0) *(float4*)&g_agg[w * 64 + fq * 4] = acc;
}

// ------ mlp_post: xout = relu( relu(agg+b1r)@W2r + h_root@W2o + b2r+b2o ) ------
#define PO_WR 0       // 4096
#define PO_WO 4096    // 4096
#define PO_A  8192    // 2048 : [g][k][s] = g*512 + k*8 + s
#define PO_H  10240   // 2048
#define PO_B1 12288   // 64
#define PO_SMEM ((12288 + 64) * 4)

__global__ void mlp_post_k(const float* __restrict__ W2r, const float* __restrict__ b2r,
                           const float* __restrict__ W2o, const float* __restrict__ b2o,
                           const float* __restrict__ b1r,
                           const int* __restrict__ batch, int last) {
    extern __shared__ float sm[];
    int tid = threadIdx.x;
    for (int i = tid; i < 4096; i += 256) { sm[PO_WR + i] = W2r[i]; sm[PO_WO + i] = W2o[i]; }
    if (tid < 64) sm[PO_B1 + tid] = b1r[tid];
    int j = tid & 63, grp = tid >> 6;
    float b2 = b2r[j] + b2o[j];
    __syncthreads();
    for (int chunk = blockIdx.x; chunk < NCHUNK; chunk += gridDim.x) {
        int base = chunk * 32;
        __syncthreads();
        for (int idx = tid; idx < 2048; idx += 256) {
            int nd = idx >> 6, k = idx & 63;
            int node = base + nd;
            float a = 0.f, h = 0.f;
            if (node < NN) {
                a = fmaxf(g_agg[node * 64 + k] + sm[PO_B1 + k], 0.f);
                h = g_hroot[node * 64 + k];
            }
            sm[PO_A + (nd >> 3) * 512 + k * 8 + (nd & 7)] = a;
            sm[PO_H + (nd >> 3) * 512 + k * 8 + (nd & 7)] = h;
        }
        __syncthreads();
        u64 bp = pack2(b2, b2);
        u64 c0 = bp, c1 = bp, c2 = bp, c3 = bp;
        const float* pa = &sm[PO_A + grp * 512];
        const float* ph = &sm[PO_H + grp * 512];
        #pragma unroll 16
        for (int k = 0; k < 64; k++) {
            ulonglong2 va = *(const ulonglong2*)(pa + k * 8);
            ulonglong2 vb = *(const ulonglong2*)(pa + k * 8 + 4);
            ulonglong2 ha = *(const ulonglong2*)(ph + k * 8);
            ulonglong2 hb = *(const ulonglong2*)(ph + k * 8 + 4);
            float wrs = sm[PO_WR + k * 64 + j];
            float wos = sm[PO_WO + k * 64 + j];
            u64 wr = pack2(wrs, wrs), wo = pack2(wos, wos);
            ffma2(c0, va.x, wr); ffma2(c1, va.y, wr); ffma2(c2, vb.x, wr); ffma2(c3, vb.y, wr);
            ffma2(c0, ha.x, wo); ffma2(c1, ha.y, wo); ffma2(c2, hb.x, wo); ffma2(c3, hb.y, wo);
        }
        int nb = base + grp * 8;
        if (nb < NN) {
            float v[8];
            unpack2(c0, v[0], v[1]); unpack2(c1, v[2], v[3]);
            unpack2(c2, v[4], v[5]); unpack2(c3, v[6], v[7]);
            if (!last) {
                #pragma unroll
                for (int s = 0; s < 8; s++)
                    g_xout[(nb + s) * 64 + j] = fmaxf(v[s], 0.f);
            } else {
                #pragma unroll
                for (int s = 0; s < 8; s++)
                    atomicAdd(&g_pooled[batch[nb + s] * 64 + j], fmaxf(v[s], 0.f));
            }
        }
    }
}

// ---------------- final MLP ----------------
__global__ void fin_k(const float* __restrict__ W1, const float* __restrict__ b1,
                      const float* __restrict__ W2, const float* __restrict__ b2,
                      float* __restrict__ out) {
    __shared__ float p[64], h[64];
    int g = blockIdx.x, t = threadIdx.x;
    p[t] = g_pooled[g * 64 + t];
    __syncthreads();
    float a = b1[t];
    #pragma unroll
    for (int k = 0; k < 64; k++) a = fmaf(p[k], W1[k * 64 + t], a);
    h[t] = fmaxf(a, 0.f);
    __syncthreads();
    if (t < OUTC) {
        float o = b2[t];
        #pragma unroll
        for (int k = 0; k < 64; k++) o = fmaf(h[k], W2[k * OUTC + t], o);
        out[g * OUTC + t] = o;
    }
}

// ---------------- launch ----------------
extern "C" void kernel_launch(void* const* d_in, const int* in_sizes, int n_in,
                              void* d_out, int out_size) {
    const float* x  = (const float*)d_in[0];
    const float* ea = (const float*)d_in[1];
    const float* L[2][8];
    for (int l = 0; l < 2; l++)
        for (int i = 0; i < 8; i++)
            L[l][i] = (const float*)d_in[2 + l * 8 + i];
    const float* finW1 = (const float*)d_in[18];
    const float* finb1 = (const float*)d_in[19];
    const float* finW2 = (const float*)d_in[20];
    const float* finb2 = (const float*)d_in[21];
    const int* ei    = (const int*)d_in[22];
    const int* batch = (const int*)d_in[23];
    float* out = (float*)d_out;

    cudaFuncSetAttribute(mlp_pre_k, cudaFuncAttributeMaxDynamicSharedMemorySize, PRE_SMEM);
    cudaFuncSetAttribute(mlp_post_k, cudaFuncAttributeMaxDynamicSharedMemorySize, PO_SMEM);

    void* cntp = 0; void* poolp = 0;
    cudaGetSymbolAddress(&cntp, g_cnt);
    cudaGetSymbolAddress(&poolp, g_pooled);
    cudaMemsetAsync(cntp, 0, 2 * NN * sizeof(int));
    cudaMemsetAsync(poolp, 0, GG * 64 * sizeof(float));

    fill_k<<<(EE / 4 + 255) / 256, 256>>>(ei);
    eagg_k<<<6250, 256>>>(ea);

    for (int l = 0; l < 2; l++) {
        mlp_pre_k<<<444, 256, PRE_SMEM>>>(x, l, L[l][0], L[l][4], L[l][5]);
        gather_k<<<6250, 256>>>();
        mlp_post_k<<<592, 256, PO_SMEM>>>(L[l][2], L[l][3], L[l][6], L[l][7],
                                          L[l][1], batch, l == 1);
    }
    fin_k<<<GG, 64>>>(finW1, finb1, finW2, finb2, out);
}

// round 14
// speedup vs baseline: 1.0278x; 1.0201x over previous
#include <cuda_runtime.h>
#include <cuda_fp16.h>

typedef unsigned long long u64;

#define NN 50000
#define EE 1600000
#define GG 256
#define OUTC 10
#define PAD 128
#define NCHUNK 1563        // ceil(50000/32)

// ---------------- device scratch ----------------
__device__ int g_cnt[2 * NN];          // [0:NN)=row counts, [NN:2NN)=col counts
__device__ int g_padr[NN * PAD];       // edge ids by source (row)
__device__ int g_padc[NN * PAD];       // source node ids by target (col)
__device__ float g_eagg[NN * 32];      // segment_sum(edge_attr, row) — layer-invariant
__device__ __half g_yrelh[NN * 64];    // xc @ W1r, fp16 row-major (gather payload)
__device__ float g_hroot[NN * 64];     // relu(xc @ W1o + b1o)
__device__ float g_agg[NN * 64];       // aggregated y_rel (f32)
__device__ float g_xout[NN * 64];
__device__ float g_pooled[GG * 64];

struct alignas(8) h2x2 { __half2 a, b; };

// ---------------- f32x2 helpers ----------------
__device__ __forceinline__ u64 pack2(float lo, float hi) {
    u64 r; asm("mov.b64 %0, {%1,%2};" : "=l"(r) : "f"(lo), "f"(hi)); return r;
}
__device__ __forceinline__ void unpack2(u64 v, float& lo, float& hi) {
    asm("mov.b64 {%0,%1}, %2;" : "=f"(lo), "=f"(hi) : "l"(v));
}
__device__ __forceinline__ void ffma2(u64& d, u64 a, u64 b) {
    asm("fma.rn.f32x2 %0, %1, %2, %0;" : "+l"(d) : "l"(a), "l"(b));
}

// ---------------- padded-bin CSR fill (scalar; 1 edge/thread) ----------------
__global__ void fill_k(const int* __restrict__ ei) {
    int e = blockIdx.x * blockDim.x + threadIdx.x;
    if (e < EE) {
        int r = ei[e], c = ei[EE + e];
        int p = atomicAdd(&g_cnt[r], 1);
        if (p < PAD) g_padr[r * PAD + p] = e;
        int q = atomicAdd(&g_cnt[NN + c], 1);
        if (q < PAD) g_padc[c * PAD + q] = r;
    }
}

// ------- edge-attr aggregation: 16 edges/warp-trip, 8 lanes x float4 per edge -------
__global__ void eagg_k(const float* __restrict__ ea) {
    int w = (blockIdx.x * blockDim.x + threadIdx.x) >> 5;
    int lane = threadIdx.x & 31;
    if (w >= NN) return;
    int c = min(g_cnt[w], PAD);
    const int* lst = &g_padr[w * PAD];
    int quad = lane >> 3;        // edge slot 0..3
    int fq = lane & 7;           // float4 index within 32-float row
    float4 acc = make_float4(0.f, 0.f, 0.f, 0.f);
    int k = 0;
    for (; k + 16 <= c; k += 16) {
        int e0 = lst[k + quad];
        int e1 = lst[k + 4 + quad];
        int e2 = lst[k + 8 + quad];
        int e3 = lst[k + 12 + quad];
        float4 v0 = *(const float4*)&ea[e0 * 32 + fq * 4];
        float4 v1 = *(const float4*)&ea[e1 * 32 + fq * 4];
        float4 v2 = *(const float4*)&ea[e2 * 32 + fq * 4];
        float4 v3 = *(const float4*)&ea[e3 * 32 + fq * 4];
        acc.x += (v0.x + v1.x) + (v2.x + v3.x);
        acc.y += (v0.y + v1.y) + (v2.y + v3.y);
        acc.z += (v0.z + v1.z) + (v2.z + v3.z);
        acc.w += (v0.w + v1.w) + (v2.w + v3.w);
    }
    for (; k + 4 <= c; k += 4) {
        int e0 = lst[k + quad];
        float4 v0 = *(const float4*)&ea[e0 * 32 + fq * 4];
        acc.x += v0.x; acc.y += v0.y; acc.z += v0.z; acc.w += v0.w;
    }
    int rem = c - k;
    if (quad < rem) {
        int e0 = lst[k + quad];
        float4 v0 = *(const float4*)&ea[e0 * 32 + fq * 4];
        acc.x += v0.x; acc.y += v0.y; acc.z += v0.z; acc.w += v0.w;
    }
    #pragma unroll
    for (int d = 8; d <= 16; d <<= 1) {
        acc.x += __shfl_xor_sync(0xffffffffu, acc.x, d);
        acc.y += __shfl_xor_sync(0xffffffffu, acc.y, d);
        acc.z += __shfl_xor_sync(0xffffffffu, acc.z, d);
        acc.w += __shfl_xor_sync(0xffffffffu, acc.w, d);
    }
    if (quad == 0) *(float4*)&g_eagg[w * 32 + fq * 4] = acc;
}

// ---------------- mlp_pre: y_rel(fp16) = xc@W1r ; h_root = relu(xc@W1o + b1o) ----------------
#define PRE_WR 0        // 6144 floats
#define PRE_WO 6144     // 6144
#define PRE_IN 12288    // 3072 : [g][k][s] = g*768 + k*8 + s
#define PRE_SMEM ((12288 + 3072) * 4)

__global__ void mlp_pre_k(const float* __restrict__ xprev, int use_xout,
                          const float* __restrict__ W1r,
                          const float* __restrict__ W1o,
                          const float* __restrict__ b1o) {
    extern __shared__ float sm[];
    const float* xin = use_xout ? g_xout : xprev;
    int tid = threadIdx.x;
    for (int i = tid; i < 6144; i += 256) { sm[PRE_WR + i] = W1r[i]; sm[PRE_WO + i] = W1o[i]; }
    int j = tid & 63, grp = tid >> 6;
    float bo = b1o[j];
    __syncthreads();
    for (int chunk = blockIdx.x; chunk < NCHUNK; chunk += gridDim.x) {
        int base = chunk * 32;
        __syncthreads();
        for (int idx = tid; idx < 3072; idx += 256) {
            int nd = idx / 96, k = idx - nd * 96;
            int node = base + nd;
            float v = 0.f;
            if (node < NN) v = (k < 64) ? xin[node * 64 + k] : g_eagg[node * 32 + (k - 64)];
            sm[PRE_IN + (nd >> 3) * 768 + k * 8 + (nd & 7)] = v;
        }
        __syncthreads();
        u64 r0 = 0, r1 = 0, r2 = 0, r3 = 0;
        u64 bop = pack2(bo, bo);
        u64 o0 = bop, o1 = bop, o2 = bop, o3 = bop;
        const float* pin = &sm[PRE_IN + grp * 768];
        #pragma unroll 12
        for (int k = 0; k < 96; k++) {
            ulonglong2 va = *(const ulonglong2*)(pin + k * 8);
            ulonglong2 vb = *(const ulonglong2*)(pin + k * 8 + 4);
            float wrs = sm[PRE_WR + k * 64 + j];
            float wos = sm[PRE_WO + k * 64 + j];
            u64 wr = pack2(wrs, wrs), wo = pack2(wos, wos);
            ffma2(r0, va.x, wr); ffma2(r1, va.y, wr); ffma2(r2, vb.x, wr); ffma2(r3, vb.y, wr);
            ffma2(o0, va.x, wo); ffma2(o1, va.y, wo); ffma2(o2, vb.x, wo); ffma2(o3, vb.y, wo);
        }
        int nb = base + grp * 8;
        if (nb < NN) {     // 50000 % 8 == 0: group fully in-range or fully out
            float v[8];
            unpack2(r0, v[0], v[1]); unpack2(r1, v[2], v[3]);
            unpack2(r2, v[4], v[5]); unpack2(r3, v[6], v[7]);
            bool even = (j & 1) == 0;
            #pragma unroll
            for (int i = 0; i < 8; i++) {
                float other = __shfl_down_sync(0xffffffffu, v[i], 1);
                if (even)
                    *(__half2*)&g_yrelh[(nb + i) * 64 + j] = __floats2half2_rn(v[i], other);
            }
            float a, b;
            unpack2(o0, a, b); g_hroot[(nb + 0) * 64 + j] = fmaxf(a, 0.f); g_hroot[(nb + 1) * 64 + j] = fmaxf(b, 0.f);
            unpack2(o1, a, b); g_hroot[(nb + 2) * 64 + j] = fmaxf(a, 0.f); g_hroot[(nb + 3) * 64 + j] = fmaxf(b, 0.f);
            unpack2(o2, a, b); g_hroot[(nb + 4) * 64 + j] = fmaxf(a, 0.f); g_hroot[(nb + 5) * 64 + j] = fmaxf(b, 0.f);
            unpack2(o3, a, b); g_hroot[(nb + 6) * 64 + j] = fmaxf(a, 0.f); g_hroot[(nb + 7) * 64 + j] = fmaxf(b, 0.f);
        }
    }
}

// ------- gather: 16 edges/warp-trip (8 per half-warp slot), fp16 depth-3 tree,
//         f32 accumulation of 8-edge partial sums -------
__global__ void gather_k() {
    int w = (blockIdx.x * blockDim.x + threadIdx.x) >> 5;
    int lane = threadIdx.x & 31;
    if (w >= NN) return;
    int c = min(g_cnt[NN + w], PAD);
    const int* lst = &g_padc[w * PAD];
    int half = lane >> 4;        // edge slot 0..1
    int fq = lane & 15;          // 4-half group index within 64-half row
    float4 acc = make_float4(0.f, 0.f, 0.f, 0.f);
    int k = 0;
    for (; k + 16 <= c; k += 16) {
        int s0 = lst[k + half];
        int s1 = lst[k + 2 + half];
        int s2 = lst[k + 4 + half];
        int s3 = lst[k + 6 + half];
        int s4 = lst[k + 8 + half];
        int s5 = lst[k + 10 + half];
        int s6 = lst[k + 12 + half];
        int s7 = lst[k + 14 + half];
        h2x2 v0 = *(const h2x2*)&g_yrelh[s0 * 64 + fq * 4];
        h2x2 v1 = *(const h2x2*)&g_yrelh[s1 * 64 + fq * 4];
        h2x2 v2 = *(const h2x2*)&g_yrelh[s2 * 64 + fq * 4];
        h2x2 v3 = *(const h2x2*)&g_yrelh[s3 * 64 + fq * 4];
        h2x2 v4 = *(const h2x2*)&g_yrelh[s4 * 64 + fq * 4];
        h2x2 v5 = *(const h2x2*)&g_yrelh[s5 * 64 + fq * 4];
        h2x2 v6 = *(const h2x2*)&g_yrelh[s6 * 64 + fq * 4];
        h2x2 v7 = *(const h2x2*)&g_yrelh[s7 * 64 + fq * 4];
        __half2 sa = __hadd2(__hadd2(__hadd2(v0.a, v1.a), __hadd2(v2.a, v3.a)),
                             __hadd2(__hadd2(v4.a, v5.a), __hadd2(v6.a, v7.a)));
        __half2 sb = __hadd2(__hadd2(__hadd2(v0.b, v1.b), __hadd2(v2.b, v3.b)),
                             __hadd2(__hadd2(v4.b, v5.b), __hadd2(v6.b, v7.b)));
        float2 fa = __half22float2(sa);
        float2 fb = __half22float2(sb);
        acc.x += fa.x; acc.y += fa.y; acc.z += fb.x; acc.w += fb.y;
    }
    for (; k + 8 <= c; k += 8) {
        int s0 = lst[k + half];
        int s1 = lst[k + 2 + half];
        int s2 = lst[k + 4 + half];
        int s3 = lst[k + 6 + half];
        h2x2 v0 = *(const h2x2*)&g_yrelh[s0 * 64 + fq * 4];
        h2x2 v1 = *(const h2x2*)&g_yrelh[s1 * 64 + fq * 4];
        h2x2 v2 = *(const h2x2*)&g_yrelh[s2 * 64 + fq * 4];
        h2x2 v3 = *(const h2x2*)&g_yrelh[s3 * 64 + fq * 4];
        __half2 sa = __hadd2(__hadd2(v0.a, v1.a), __hadd2(v2.a, v3.a));
        __half2 sb = __hadd2(__hadd2(v0.b, v1.b), __hadd2(v2.b, v3.b));
        float2 fa = __half22float2(sa);
        float2 fb = __half22float2(sb);
        acc.x += fa.x; acc.y += fa.y; acc.z += fb.x; acc.w += fb.y;
    }
    for (; k + 2 <= c; k += 2) {
        int s0 = lst[k + half];
        h2x2 v0 = *(const h2x2*)&g_yrelh[s0 * 64 + fq * 4];
        float2 fa = __half22float2(v0.a), fb = __half22float2(v0.b);
        acc.x += fa.x; acc.y += fa.y; acc.z += fb.x; acc.w += fb.y;
    }
    if (k < c && half == 0) {
        int s0 = lst[k];
        h2x2 v0 = *(const h2x2*)&g_yrelh[s0 * 64 + fq * 4];
        float2 fa = __half22float2(v0.a), fb = __half22float2(v0.b);
        acc.x += fa.x; acc.y += fa.y; acc.z += fb.x; acc.w += fb.y;
    }
    acc.x += __shfl_xor_sync(0xffffffffu, acc.x, 16);
    acc.y += __shfl_xor_sync(0xffffffffu, acc.y, 16);
    acc.z += __shfl_xor_sync(0xffffffffu, acc.z, 16);
    acc.w += __shfl_xor_sync(0xffffffffu, acc.w, 16);
    if (half == 0) *(float4*)&g_agg[w * 64 + fq * 4] = acc;
}

// ------ mlp_post: xout = relu( relu(agg+b1r)@W2r + h_root@W2o + b2r+b2o ) ------
#define PO_WR 0       // 4096
#define PO_WO 4096    // 4096
#define PO_A  8192    // 2048 : [g][k][s] = g*512 + k*8 + s
#define PO_H  10240   // 2048
#define PO_B1 12288   // 64
#define PO_SMEM ((12288 + 64) * 4)

__global__ void mlp_post_k(const float* __restrict__ W2r, const float* __restrict__ b2r,
                           const float* __restrict__ W2o, const float* __restrict__ b2o,
                           const float* __restrict__ b1r,
                           const int* __restrict__ batch, int last) {
    extern __shared__ float sm[];
    int tid = threadIdx.x;
    for (int i = tid; i < 4096; i += 256) { sm[PO_WR + i] = W2r[i]; sm[PO_WO + i] = W2o[i]; }
    if (tid < 64) sm[PO_B1 + tid] = b1r[tid];
    int j = tid & 63, grp = tid >> 6;
    float b2 = b2r[j] + b2o[j];
    __syncthreads();
    for (int chunk = blockIdx.x; chunk < NCHUNK; chunk += gridDim.x) {
        int base = chunk * 32;
        __syncthreads();
        for (int idx = tid; idx < 2048; idx += 256) {
            int nd = idx >> 6, k = idx & 63;
            int node = base + nd;
            float a = 0.f, h = 0.f;
            if (node < NN) {
                a = fmaxf(g_agg[node * 64 + k] + sm[PO_B1 + k], 0.f);
                h = g_hroot[node * 64 + k];
            }
            sm[PO_A + (nd >> 3) * 512 + k * 8 + (nd & 7)] = a;
            sm[PO_H + (nd >> 3) * 512 + k * 8 + (nd & 7)] = h;
        }
        __syncthreads();
        u64 bp = pack2(b2, b2);
        u64 c0 = bp, c1 = bp, c2 = bp, c3 = bp;
        const float* pa = &sm[PO_A + grp * 512];
        const float* ph = &sm[PO_H + grp * 512];
        #pragma unroll 16
        for (int k = 0; k < 64; k++) {
            ulonglong2 va = *(const ulonglong2*)(pa + k * 8);
            ulonglong2 vb = *(const ulonglong2*)(pa + k * 8 + 4);
            ulonglong2 ha = *(const ulonglong2*)(ph + k * 8);
            ulonglong2 hb = *(const ulonglong2*)(ph + k * 8 + 4);
            float wrs = sm[PO_WR + k * 64 + j];
            float wos = sm[PO_WO + k * 64 + j];
            u64 wr = pack2(wrs, wrs), wo = pack2(wos, wos);
            ffma2(c0, va.x, wr); ffma2(c1, va.y, wr); ffma2(c2, vb.x, wr); ffma2(c3, vb.y, wr);
            ffma2(c0, ha.x, wo); ffma2(c1, ha.y, wo); ffma2(c2, hb.x, wo); ffma2(c3, hb.y, wo);
        }
        int nb = base + grp * 8;
        if (nb < NN) {
            float v[8];
            unpack2(c0, v[0], v[1]); unpack2(c1, v[2], v[3]);
            unpack2(c2, v[4], v[5]); unpack2(c3, v[6], v[7]);
            if (!last) {
                #pragma unroll
                for (int s = 0; s < 8; s++)
                    g_xout[(nb + s) * 64 + j] = fmaxf(v[s], 0.f);
            } else {
                #pragma unroll
                for (int s = 0; s < 8; s++)
                    atomicAdd(&g_pooled[batch[nb + s] * 64 + j], fmaxf(v[s], 0.f));
            }
        }
    }
}

// ---------------- final MLP ----------------
__global__ void fin_k(const float* __restrict__ W1, const float* __restrict__ b1,
                      const float* __restrict__ W2, const float* __restrict__ b2,
                      float* __restrict__ out) {
    __shared__ float p[64], h[64];
    int g = blockIdx.x, t = threadIdx.x;
    p[t] = g_pooled[g * 64 + t];
    __syncthreads();
    float a = b1[t];
    #pragma unroll
    for (int k = 0; k < 64; k++) a = fmaf(p[k], W1[k * 64 + t], a);
    h[t] = fmaxf(a, 0.f);
    __syncthreads();
    if (t < OUTC) {
        float o = b2[t];
        #pragma unroll
        for (int k = 0; k < 64; k++) o = fmaf(h[k], W2[k * OUTC + t], o);
        out[g * OUTC + t] = o;
    }
}

// ---------------- launch ----------------
extern "C" void kernel_launch(void* const* d_in, const int* in_sizes, int n_in,
                              void* d_out, int out_size) {
    const float* x  = (const float*)d_in[0];
    const float* ea = (const float*)d_in[1];
    const float* L[2][8];
    for (int l = 0; l < 2; l++)
        for (int i = 0; i < 8; i++)
            L[l][i] = (const float*)d_in[2 + l * 8 + i];
    const float* finW1 = (const float*)d_in[18];
    const float* finb1 = (const float*)d_in[19];
    const float* finW2 = (const float*)d_in[20];
    const float* finb2 = (const float*)d_in[21];
    const int* ei    = (const int*)d_in[22];
    const int* batch = (const int*)d_in[23];
    float* out = (float*)d_out;

    cudaFuncSetAttribute(mlp_pre_k, cudaFuncAttributeMaxDynamicSharedMemorySize, PRE_SMEM);
    cudaFuncSetAttribute(mlp_post_k, cudaFuncAttributeMaxDynamicSharedMemorySize, PO_SMEM);

    void* cntp = 0; void* poolp = 0;
    cudaGetSymbolAddress(&cntp, g_cnt);
    cudaGetSymbolAddress(&poolp, g_pooled);
    cudaMemsetAsync(cntp, 0, 2 * NN * sizeof(int));
    cudaMemsetAsync(poolp, 0, GG * 64 * sizeof(float));

    fill_k<<<(EE + 255) / 256, 256>>>(ei);
    eagg_k<<<6250, 256>>>(ea);

    for (int l = 0; l < 2; l++) {
        mlp_pre_k<<<444, 256, PRE_SMEM>>>(x, l, L[l][0], L[l][4], L[l][5]);
        gather_k<<<6250, 256>>>();
        mlp_post_k<<<592, 256, PO_SMEM>>>(L[l][2], L[l][3], L[l][6], L[l][7],
                                          L[l][1], batch, l == 1);
    }
    fin_k<<<GG, 64>>>(finW1, finb1, finW2, finb2, out);
}